// round 14
// baseline (speedup 1.0000x reference)
#include <cuda_runtime.h>
#include <cuda_fp16.h>
#include <cstdint>

// ---------------------------------------------------------------- constants
#define H 128
#define BB 256
#define SS 1024
#define ROWS (BB*(SS-1))          // 261888
#define TM 64                     // rows per tile
#define NTILES (ROWS/TM)          // 4092 (exact)
#define NCTA 444                  // persistent CTAs (3/SM x 148, all resident)

#define YSTR 136                  // fp16 elems per y-tile row (272 B, padded)
#define YROWB (YSTR*2)            // 272
#define YTILE (65*YROWB)          // 17680 (65 rows: +1 for x1 of row 63)

// dynamic smem layout (bytes)
#define SM_DF   0                         // D fp16 B-frags (paired), 32768
#define SM_Y0   32768
#define SM_Y1   (SM_Y0 + YTILE)
#define SMEM_TOTAL (SM_Y1 + YTILE)        // 68128 -> 3 CTAs/SM

// ---------------------------------------------------------------- scratch
__device__ float          g_B[H*H];          // C^2
__device__ __half         g_Dfrag[H*H];      // D fp16, paired B-frag order
__device__ double         g_partials[NCTA];
__device__ double         g_l2row[H];
__device__ double         g_l2;
__device__ unsigned int   g_done;
__device__ unsigned int   g_barA;            // prep phase barrier (128)
__device__ unsigned int   g_barB;            // all-CTA barrier (444)

// ---------------------------------------------------------------- helpers
__device__ __forceinline__ uint32_t smem_u32(const void* p) {
    uint32_t a;
    asm("{ .reg .u64 t; cvta.to.shared.u64 t, %1; cvt.u32.u64 %0, t; }"
        : "=r"(a) : "l"(p));
    return a;
}

#define MMA_F16(ACC, A0, A1, A2, A3, B0, B1)                                \
    asm volatile(                                                           \
        "mma.sync.aligned.m16n8k16.row.col.f32.f16.f16.f32 "                \
        "{%0,%1,%2,%3}, {%4,%5,%6,%7}, {%8,%9}, {%0,%1,%2,%3};"             \
        : "+f"((ACC)[0]), "+f"((ACC)[1]), "+f"((ACC)[2]), "+f"((ACC)[3])    \
        : "r"(A0), "r"(A1), "r"(A2), "r"(A3), "r"(B0), "r"(B1))

__device__ __forceinline__ void cvt_store16(char* dst, float4 v0, float4 v1) {
    __half2 p0 = __floats2half2_rn(v0.x, v0.y);
    __half2 p1 = __floats2half2_rn(v0.z, v0.w);
    __half2 p2 = __floats2half2_rn(v1.x, v1.y);
    __half2 p3 = __floats2half2_rn(v1.z, v1.w);
    uint4 u;
    u.x = *(uint32_t*)&p0; u.y = *(uint32_t*)&p1;
    u.z = *(uint32_t*)&p2; u.w = *(uint32_t*)&p3;
    *(uint4*)dst = u;
}

// ---------------------------------------------------------------- fused kernel
// 444 CTAs x 256 threads, 3 CTAs/SM (launch_bounds guarantees co-residency).
// Stage 0: every CTA converts its first tile. Stage 1: CTAs 0..127 compute
// M = I + D (two phases, barrier-A). Stage 2: barrier-B (444), stage D,
// persistent mainloop with convert pipelined inside the mma loop.
__global__ void __launch_bounds__(256, 3)
fused_kernel(const float* __restrict__ x, const float* __restrict__ coeff,
             float* __restrict__ out) {
    extern __shared__ char smem[];
    const int tid = threadIdx.x;
    const int cta = blockIdx.x;
    const int vrow = tid >> 2, vq = tid & 3;   // convert mapping (64 rows x 4)

    // ================= stage 0: convert first tile -> SM_Y0 (no D needed)
    {
        int rg = cta*TM + vrow;
        int b = rg / 1023, s = rg - b*1023;
        const float4* src = (const float4*)(x + (size_t)(b*SS + s)*H) + vq*8;
        char* dst = smem + SM_Y0 + (size_t)vrow*YROWB + vq*64;
        #pragma unroll
        for (int q = 0; q < 4; q++)
            cvt_store16(dst + q*16, src[2*q], src[2*q + 1]);
        if (tid < 32) {   // row 64 = x1 of row 63 (32 parallel LDGs)
            int rg7 = cta*TM + 63;
            int b7 = rg7 / 1023, s7 = rg7 - b7*1023;
            float4 v = *((const float4*)(x + (size_t)(b7*SS + s7 + 1)*H) + tid);
            __half2 p0 = __floats2half2_rn(v.x, v.y);
            __half2 p1 = __floats2half2_rn(v.z, v.w);
            uint2 u; u.x = *(uint32_t*)&p0; u.y = *(uint32_t*)&p1;
            *(uint2*)(smem + SM_Y0 + (size_t)64*YROWB + tid*8) = u;
        }
    }

    // ================= stage 1: prep (CTAs 0..127), smem overlaid on SM_Y1
    if (cta < H) {
        float* crow  = (float*)(smem + SM_Y1);
        float* brow  = crow + H;
        float* c2row = brow + H;
        float* part  = c2row + H;          // [2][H]
        const int i  = cta;
        const int j  = tid & 127;
        const int kh = tid >> 7;           // 0/1: k-half

        if (tid < H) crow[tid] = coeff[i*H + tid];
        __syncthreads();

        {   // phase 1: B[i][j] = sum_k crow[k] * C[k][j]
            float a0=0.f, a1=0.f, a2=0.f, a3=0.f;
            int k0 = kh * 64;
            #pragma unroll
            for (int k = 0; k < 64; k += 4) {
                a0 = fmaf(crow[k0+k],   __ldg(coeff + (k0+k)*H + j),   a0);
                a1 = fmaf(crow[k0+k+1], __ldg(coeff + (k0+k+1)*H + j), a1);
                a2 = fmaf(crow[k0+k+2], __ldg(coeff + (k0+k+2)*H + j), a2);
                a3 = fmaf(crow[k0+k+3], __ldg(coeff + (k0+k+3)*H + j), a3);
            }
            part[kh*H + j] = (a0+a1) + (a2+a3);
        }
        __syncthreads();
        if (tid < H) {
            float b = part[tid] + part[H + tid];
            g_B[i*H + tid] = b;
            brow[tid]  = b;
            c2row[tid] = crow[tid]*(1.0f/6.0f) + b*(1.0f/24.0f);
        }
        {   // per-row l2 partial
            float v = 0.f;
            if (tid < H) { float c = crow[tid], cc = c*c; v = cc*cc; }
            #pragma unroll
            for (int off = 16; off; off >>= 1)
                v += __shfl_down_sync(0xffffffffu, v, off);
            __shared__ float lred[8];
            if ((tid & 31) == 0) lred[tid >> 5] = v;
            __syncthreads();
            if (tid == 0) {
                float s = 0.f;
                #pragma unroll
                for (int q = 0; q < 8; q++) s += lred[q];
                g_l2row[i] = (double)s;
            }
        }

        // barrier-A over the 128 prep CTAs
        __threadfence();
        __syncthreads();
        if (tid == 0) {
            atomicAdd(&g_barA, 1u);
            while (*(volatile unsigned int*)&g_barA < (unsigned int)H) { }
        }
        __syncthreads();
        __threadfence();

        {   // phase 2: D[i][j] = crow + B/2 + c2row @ B
            float a0=0.f, a1=0.f, a2=0.f, a3=0.f;
            int k0 = kh * 64;
            #pragma unroll
            for (int k = 0; k < 64; k += 4) {
                a0 = fmaf(c2row[k0+k],   __ldg(g_B + (k0+k)*H + j),   a0);
                a1 = fmaf(c2row[k0+k+1], __ldg(g_B + (k0+k+1)*H + j), a1);
                a2 = fmaf(c2row[k0+k+2], __ldg(g_B + (k0+k+2)*H + j), a2);
                a3 = fmaf(c2row[k0+k+3], __ldg(g_B + (k0+k+3)*H + j), a3);
            }
            part[kh*H + j] = (a0+a1) + (a2+a3);
        }
        __syncthreads();
        if (tid < H) {
            float d = crow[tid] + 0.5f*brow[tid] + (part[tid] + part[H + tid]);
            // paired m16n8k16 B-frag scatter (i = n, tid = k)
            int ks = tid >> 4, kin = tid & 15;
            int reg = kin >> 3;
            int lane = ((i & 7) << 2) + ((kin & 7) >> 1);
            int fidx = (((ks*8 + (i >> 4))*32 + lane) << 3)
                     + (((i >> 3) & 1) << 2) + (reg << 1) + (tid & 1);
            g_Dfrag[fidx] = __float2half_rn(d);
        }
        if (i == 0 && tid == 0) {
            double s = 0.0;
            #pragma unroll
            for (int r = 0; r < H; r++) s += g_l2row[r];
            g_l2 = s;
        }
    }

    // ================= stage 2: barrier-B over ALL 444 CTAs
    __threadfence();
    __syncthreads();
    if (tid == 0) {
        atomicAdd(&g_barB, 1u);
        while (*(volatile unsigned int*)&g_barB < (unsigned int)NCTA) { }
    }
    __syncthreads();
    __threadfence();

    // ---- stage D B-fragments once, 32KB
    {
        const uint4* df = (const uint4*)g_Dfrag;
        uint4* sh = (uint4*)(smem + SM_DF);
        #pragma unroll
        for (int q = 0; q < 8; q++) sh[tid + q*256] = df[tid + q*256];
    }
    __syncthreads();          // also publishes stage-0 tile0 converts

    // ================= persistent mainloop
    const int w    = tid >> 5;
    const int lane = tid & 31;
    const int rb   = (w & 3) * 16;       // row base (1 m16 tile)
    const int cb   = (w >> 2) * 8;       // n-tile base (8 tiles = 64 cols)
    const int pb   = cb >> 1;            // n-pair base (4 pairs)

    double csum = 0.0;
    int buf = 0;

    for (int tile = cta; tile < NTILES; tile += NCTA) {
        char* ycur = smem + (buf ? SM_Y1 : SM_Y0);
        char* ynxt = smem + (buf ? SM_Y0 : SM_Y1);

        const int ntile = tile + NCTA;
        const bool has_next = (ntile < NTILES);
        const float4* nsrc = (const float4*)x;
        char* ndst = ynxt + (size_t)vrow*YROWB + vq*64;
        if (has_next) {
            int rg = ntile*TM + vrow;
            int b = rg / 1023, s = rg - b*1023;
            nsrc = (const float4*)(x + (size_t)(b*SS + s)*H) + vq*8;
        }

        float acc[8][4];
        #pragma unroll
        for (int t = 0; t < 8; t++) {
            acc[t][0] = 0.f; acc[t][1] = 0.f;
            acc[t][2] = 0.f; acc[t][3] = 0.f;
        }
        const uint32_t abase = smem_u32(ycur)
            + (uint32_t)((rb + (lane & 15))*YSTR + (lane >> 4)*8)*2;

        // ---- mma loop with pipelined next-tile convert
        // even ks: load 2 float4 of next tile; odd ks: convert+store them.
        float4 pf0, pf1;

        #pragma unroll
        for (int ks = 0; ks < 8; ks++) {
            if (has_next) {
                if ((ks & 1) == 0) { pf0 = nsrc[ks]; pf1 = nsrc[ks + 1]; }
            }

            uint4 bf[4];
            #pragma unroll
            for (int pp = 0; pp < 4; pp++) {
                uint32_t foff = (uint32_t)(((ks*8 + pb + pp)*32 + lane) * 16);
                bf[pp] = *(const uint4*)(smem + SM_DF + foff);
            }
            uint32_t a0, a1, a2, a3;
            asm volatile("ldmatrix.sync.aligned.m8n8.x4.shared.b16 {%0,%1,%2,%3}, [%4];"
                         : "=r"(a0), "=r"(a1), "=r"(a2), "=r"(a3)
                         : "r"(abase + ks*32));
            #pragma unroll
            for (int pp = 0; pp < 4; pp++) {
                MMA_F16(acc[2*pp+0], a0, a1, a2, a3, bf[pp].x, bf[pp].y);
                MMA_F16(acc[2*pp+1], a0, a1, a2, a3, bf[pp].z, bf[pp].w);
            }

            if (has_next && (ks & 1)) cvt_store16(ndst + (ks >> 1)*16, pf0, pf1);
        }

        // ---- row 64 of next tile (x1 of its row 63), 32 parallel LDGs
        if (has_next && tid < 32) {
            int rg7 = ntile*TM + 63;
            int b7 = rg7 / 1023, s7 = rg7 - b7*1023;
            float4 v = *((const float4*)(x + (size_t)(b7*SS + s7 + 1)*H) + tid);
            __half2 p0 = __floats2half2_rn(v.x, v.y);
            __half2 p1 = __floats2half2_rn(v.z, v.w);
            uint2 u; u.x = *(uint32_t*)&p0; u.y = *(uint32_t*)&p1;
            *(uint2*)(ynxt + (size_t)64*YROWB + tid*8) = u;
        }

        // ---- epilogue: d = y + P - x1, y/x1 fp16 from smem rows r / r+1
        float lsum = 0.f;
        #pragma unroll
        for (int rr = 0; rr < 2; rr++) {
            int r  = rb + rr*8 + (lane >> 2);
            int rg = tile*TM + r;
            int b  = rg / 1023;
            int s  = rg - b*1023;
            const char* yrow  = ycur + (size_t)r*YROWB + (lane & 3)*4;
            const char* x1row = yrow + YROWB;
            bool bnd = (s == 1022);
            const float* gx1 = x + (size_t)(b*SS + s + 1)*H;
            #pragma unroll
            for (int t = 0; t < 8; t++) {
                float2 yf = __half22float2(*(const __half2*)(yrow + (cb + t)*16));
                float2 xf;
                if (bnd) {
                    xf = *(const float2*)(gx1 + (cb + t)*8 + (lane & 3)*2);
                } else {
                    xf = __half22float2(*(const __half2*)(x1row + (cb + t)*16));
                }
                float d;
                d = yf.x + acc[t][rr*2+0] - xf.x; lsum = fmaf(d, d, lsum);
                d = yf.y + acc[t][rr*2+1] - xf.y; lsum = fmaf(d, d, lsum);
            }
        }
        csum += (double)lsum;

        __syncthreads();      // ycur reads + ynxt writes complete
        buf ^= 1;
    }

    // ================= final reduction (fixed order -> deterministic)
    #pragma unroll
    for (int off = 16; off; off >>= 1)
        csum += __shfl_down_sync(0xffffffffu, csum, off);
    __shared__ double redd[8];
    if (lane == 0) redd[w] = csum;
    __syncthreads();

    __shared__ bool is_last;
    if (tid == 0) {
        double s = 0.0;
        #pragma unroll
        for (int q = 0; q < 8; q++) s += redd[q];
        g_partials[cta] = s;
        __threadfence();
        unsigned int old = atomicAdd(&g_done, 1u);
        is_last = (old == (unsigned int)(NCTA - 1));
    }
    __syncthreads();

    if (is_last) {
        double s = (tid < NCTA) ? g_partials[tid] : 0.0;
        if (tid + 256 < NCTA) s += g_partials[tid + 256];
        __shared__ double sd[256];
        sd[tid] = s; __syncthreads();
        for (int off = 128; off; off >>= 1) {
            if (tid < off) sd[tid] += sd[tid + off];
            __syncthreads();
        }
        if (tid == 0) {
            double step_loss = sd[0] / ((double)ROWS * (double)H);
            double l2_loss   = g_l2 / ((double)H * (double)H);
            out[0] = (float)(step_loss + 0.001 * l2_loss);
            g_done = 0u; g_barA = 0u; g_barB = 0u;   // reset for graph replay
        }
    }
}

// ---------------------------------------------------------------- launch
extern "C" void kernel_launch(void* const* d_in, const int* in_sizes, int n_in,
                              void* d_out, int out_size) {
    const float* x     = (const float*)d_in[0];
    const float* coeff = (const float*)d_in[1];
    if (n_in >= 2 && in_sizes[0] == H*H) {
        coeff = (const float*)d_in[0];
        x     = (const float*)d_in[1];
    }
    float* out = (float*)d_out;

    cudaFuncSetAttribute(fused_kernel,
                         cudaFuncAttributeMaxDynamicSharedMemorySize, SMEM_TOTAL);

    fused_kernel<<<NCTA, 256, SMEM_TOTAL>>>(x, coeff, out);
}

// round 15
// speedup vs baseline: 1.0048x; 1.0048x over previous
#include <cuda_runtime.h>
#include <cuda_fp16.h>
#include <cstdint>

// ---------------------------------------------------------------- constants
#define H 128
#define BB 256
#define SS 1024
#define ROWS (BB*(SS-1))          // 261888
#define TM 128                    // rows per tile
#define NTILES (ROWS/TM)          // 2046 (exact)
#define NCTA 296                  // persistent CTAs (2/SM x 148, all resident)
#define NPREP 256                 // prep CTAs (row x col-half)

#define YSTR 136                  // fp16 elems per y-tile row (272 B, padded)
#define YROWB (YSTR*2)            // 272
#define YTILE (129*YROWB)         // 35088 (129 rows: +1 for x1 of row 127)

// dynamic smem layout (bytes)
#define SM_DF   0                         // D fp16 B-frags (paired), 32768
#define SM_Y0   32768
#define SM_Y1   (SM_Y0 + YTILE)
#define SMEM_TOTAL (SM_Y1 + YTILE)        // 102944 -> 2 CTAs/SM

// ---------------------------------------------------------------- scratch
__device__ float          g_B[H*H];          // C^2
__device__ __half         g_Dfrag[H*H];      // D fp16, paired B-frag order
__device__ double         g_partials[NCTA];
__device__ double         g_l2row[H];
__device__ double         g_l2;
__device__ unsigned int   g_done;
__device__ unsigned int   g_barA;            // prep phase barrier (256)
__device__ unsigned int   g_barB;            // all-CTA barrier (296)

// ---------------------------------------------------------------- helpers
__device__ __forceinline__ uint32_t smem_u32(const void* p) {
    uint32_t a;
    asm("{ .reg .u64 t; cvta.to.shared.u64 t, %1; cvt.u32.u64 %0, t; }"
        : "=r"(a) : "l"(p));
    return a;
}

#define MMA_F16(ACC, A0, A1, A2, A3, B0, B1)                                \
    asm volatile(                                                           \
        "mma.sync.aligned.m16n8k16.row.col.f32.f16.f16.f32 "                \
        "{%0,%1,%2,%3}, {%4,%5,%6,%7}, {%8,%9}, {%0,%1,%2,%3};"             \
        : "+f"((ACC)[0]), "+f"((ACC)[1]), "+f"((ACC)[2]), "+f"((ACC)[3])    \
        : "r"(A0), "r"(A1), "r"(A2), "r"(A3), "r"(B0), "r"(B1))

__device__ __forceinline__ void cvt_store16(char* dst, float4 v0, float4 v1) {
    __half2 p0 = __floats2half2_rn(v0.x, v0.y);
    __half2 p1 = __floats2half2_rn(v0.z, v0.w);
    __half2 p2 = __floats2half2_rn(v1.x, v1.y);
    __half2 p3 = __floats2half2_rn(v1.z, v1.w);
    uint4 u;
    u.x = *(uint32_t*)&p0; u.y = *(uint32_t*)&p1;
    u.z = *(uint32_t*)&p2; u.w = *(uint32_t*)&p3;
    *(uint4*)dst = u;
}

// ---------------------------------------------------------------- fused kernel
// 296 CTAs x 256 threads, 2 CTAs/SM, all co-resident (global barriers OK).
// Stage 0: every CTA converts its first tile -> SM_Y0.
// Stage 1: CTAs 0..255 compute M = I + D (row x col-half split; barrier-A).
// Stage 2: barrier-B (296), stage D frags, persistent mainloop with
// store->load->mma pipelined convert. Final: fused deterministic reduction.
__global__ void __launch_bounds__(256, 2)
fused_kernel(const float* __restrict__ x, const float* __restrict__ coeff,
             float* __restrict__ out) {
    extern __shared__ char smem[];
    const int tid = threadIdx.x;
    const int cta = blockIdx.x;

    // ================= stage 0: convert first tile -> SM_Y0 (no D needed)
    {
        int row = tid >> 1, half = tid & 1;
        int rg = cta*TM + row;
        int b = rg / 1023, s = rg - b*1023;
        const float4* src = (const float4*)(x + (size_t)(b*SS + s)*H) + half*16;
        char* dst = smem + SM_Y0 + (size_t)row*YROWB + half*128;
        #pragma unroll
        for (int q = 0; q < 8; q++)
            cvt_store16(dst + q*16, src[2*q], src[2*q + 1]);
        if (tid < 32) {   // row 128 = x1 of row 127 (32 parallel LDGs)
            int rg7 = cta*TM + 127;
            int b7 = rg7 / 1023, s7 = rg7 - b7*1023;
            float4 v = *((const float4*)(x + (size_t)(b7*SS + s7 + 1)*H) + tid);
            __half2 p0 = __floats2half2_rn(v.x, v.y);
            __half2 p1 = __floats2half2_rn(v.z, v.w);
            uint2 u; u.x = *(uint32_t*)&p0; u.y = *(uint32_t*)&p1;
            *(uint2*)(smem + SM_Y0 + (size_t)128*YROWB + tid*8) = u;
        }
    }

    // ================= stage 1: prep (CTAs 0..255), smem overlaid on SM_Y1
    // cta = i*2 + half : row i, cols [half*64, half*64+64). Thread (jj,kq):
    // jj = tid&63 (col in half), kq = tid>>6 (k-quarter).
    float bval = 0.f;                       // B[i][j] held by tid<64
    if (cta < NPREP) {
        float* crow  = (float*)(smem + SM_Y1);        // [128]
        float* c2row = crow + H;                      // [128]
        float* part  = c2row + H;                     // [4][64]
        const int i    = cta >> 1;
        const int half = cta & 1;
        const int jj   = tid & 63;
        const int j    = half*64 + jj;
        const int kq   = tid >> 6;

        if (tid < H) crow[tid] = coeff[i*H + tid];
        __syncthreads();

        {   // phase 1 partial: B[i][j] over k-quarter
            float a0=0.f, a1=0.f, a2=0.f, a3=0.f;
            int k0 = kq * 32;
            #pragma unroll
            for (int k = 0; k < 32; k += 4) {
                a0 = fmaf(crow[k0+k],   __ldg(coeff + (k0+k)*H + j),   a0);
                a1 = fmaf(crow[k0+k+1], __ldg(coeff + (k0+k+1)*H + j), a1);
                a2 = fmaf(crow[k0+k+2], __ldg(coeff + (k0+k+2)*H + j), a2);
                a3 = fmaf(crow[k0+k+3], __ldg(coeff + (k0+k+3)*H + j), a3);
            }
            part[kq*64 + jj] = (a0+a1) + (a2+a3);
        }
        __syncthreads();
        if (tid < 64) {
            bval = (part[tid] + part[64 + tid]) + (part[128 + tid] + part[192 + tid]);
            g_B[i*H + half*64 + tid] = bval;
        }
        if (half == 0) {   // per-row l2 partial (half-0 CTA owns it)
            float v = 0.f;
            if (tid < H) { float c = crow[tid], cc = c*c; v = cc*cc; }
            #pragma unroll
            for (int off = 16; off; off >>= 1)
                v += __shfl_down_sync(0xffffffffu, v, off);
            __shared__ float lred[8];
            if ((tid & 31) == 0) lred[tid >> 5] = v;
            __syncthreads();
            if (tid == 0) {
                float s = 0.f;
                #pragma unroll
                for (int q = 0; q < 8; q++) s += lred[q];
                g_l2row[i] = (double)s;
            }
        }

        // barrier-A over the 256 prep CTAs
        __threadfence();
        __syncthreads();
        if (tid == 0) {
            atomicAdd(&g_barA, 1u);
            while (*(volatile unsigned int*)&g_barA < (unsigned int)NPREP) { }
        }
        __syncthreads();
        __threadfence();

        // c2row = C[i]/6 + B[i]/24 (full row, from global B)
        if (tid < H)
            c2row[tid] = crow[tid]*(1.0f/6.0f) + __ldg(g_B + i*H + tid)*(1.0f/24.0f);
        __syncthreads();

        {   // phase 2 partial: (c2row @ B)[j] over k-quarter
            float a0=0.f, a1=0.f, a2=0.f, a3=0.f;
            int k0 = kq * 32;
            #pragma unroll
            for (int k = 0; k < 32; k += 4) {
                a0 = fmaf(c2row[k0+k],   __ldg(g_B + (k0+k)*H + j),   a0);
                a1 = fmaf(c2row[k0+k+1], __ldg(g_B + (k0+k+1)*H + j), a1);
                a2 = fmaf(c2row[k0+k+2], __ldg(g_B + (k0+k+2)*H + j), a2);
                a3 = fmaf(c2row[k0+k+3], __ldg(g_B + (k0+k+3)*H + j), a3);
            }
            part[kq*64 + jj] = (a0+a1) + (a2+a3);
        }
        __syncthreads();
        if (tid < 64) {
            int jfull = half*64 + tid;
            float d = crow[jfull] + 0.5f*bval
                    + ((part[tid] + part[64 + tid]) + (part[128 + tid] + part[192 + tid]));
            // paired m16n8k16 B-frag scatter (n = i, k = jfull)
            int ks = jfull >> 4, kin = jfull & 15;
            int reg = kin >> 3;
            int lane = ((i & 7) << 2) + ((kin & 7) >> 1);
            int fidx = (((ks*8 + (i >> 4))*32 + lane) << 3)
                     + (((i >> 3) & 1) << 2) + (reg << 1) + (jfull & 1);
            g_Dfrag[fidx] = __float2half_rn(d);
        }
        if (cta == 0 && tid == 0) {
            double s = 0.0;
            #pragma unroll
            for (int r = 0; r < H; r++) s += g_l2row[r];
            g_l2 = s;
        }
    }

    // ================= stage 2: barrier-B over ALL 296 CTAs
    __threadfence();
    __syncthreads();
    if (tid == 0) {
        atomicAdd(&g_barB, 1u);
        while (*(volatile unsigned int*)&g_barB < (unsigned int)NCTA) { }
    }
    __syncthreads();
    __threadfence();

    // ---- stage D B-fragments once, 32KB
    {
        const uint4* df = (const uint4*)g_Dfrag;
        uint4* sh = (uint4*)(smem + SM_DF);
        #pragma unroll
        for (int q = 0; q < 8; q++) sh[tid + q*256] = df[tid + q*256];
    }
    __syncthreads();          // also publishes stage-0 tile0 converts

    // ================= persistent mainloop
    const int w    = tid >> 5;
    const int lane = tid & 31;
    const int rb   = (w & 3) * 32;
    const int cb   = (w >> 2) * 8;
    const int pb   = cb >> 1;
    const int vrow = tid >> 1, vhalf = tid & 1;    // convert mapping

    double csum = 0.0;
    int buf = 0;

    for (int tile = cta; tile < NTILES; tile += NCTA) {
        char* ycur = smem + (buf ? SM_Y1 : SM_Y0);
        char* ynxt = smem + (buf ? SM_Y0 : SM_Y1);

        const int ntile = tile + NCTA;
        const bool has_next = (ntile < NTILES);
        const float4* nsrc = (const float4*)x;
        char* ndst = ynxt + (size_t)vrow*YROWB + vhalf*128;
        if (has_next) {
            int rg = ntile*TM + vrow;
            int b = rg / 1023, s = rg - b*1023;
            nsrc = (const float4*)(x + (size_t)(b*SS + s)*H) + vhalf*16;
        }

        float acc[2][8][4];
        #pragma unroll
        for (int rt = 0; rt < 2; rt++)
            #pragma unroll
            for (int t = 0; t < 8; t++) {
                acc[rt][t][0] = 0.f; acc[rt][t][1] = 0.f;
                acc[rt][t][2] = 0.f; acc[rt][t][3] = 0.f;
            }
        const uint32_t abase = smem_u32(ycur)
            + (uint32_t)((rb + (lane & 15))*YSTR + (lane >> 4)*8)*2;

        // ---- convert pipeline: chunk ks stored at iter ks, replacement
        // (chunk ks+2) loaded right after the store -> ~2 mma bodies of
        // latency cover; 2 buffers (16 regs), same liveness as before.
        float4 pf[2][2];
        if (has_next) {
            pf[0][0] = nsrc[0]; pf[0][1] = nsrc[1];     // chunk 0
            pf[1][0] = nsrc[2]; pf[1][1] = nsrc[3];     // chunk 1
        }

        #pragma unroll
        for (int ks = 0; ks < 8; ks++) {
            const int par = ks & 1;
            if (has_next) {
                cvt_store16(ndst + ks*16, pf[par][0], pf[par][1]);
                if (ks < 6) {
                    pf[par][0] = nsrc[2*ks + 4];        // chunk ks+2
                    pf[par][1] = nsrc[2*ks + 5];
                }
            }

            uint4 bf[4];
            #pragma unroll
            for (int pp = 0; pp < 4; pp++) {
                uint32_t foff = (uint32_t)(((ks*8 + pb + pp)*32 + lane) * 16);
                bf[pp] = *(const uint4*)(smem + SM_DF + foff);
            }
            #pragma unroll
            for (int rt = 0; rt < 2; rt++) {
                uint32_t a0, a1, a2, a3;
                asm volatile("ldmatrix.sync.aligned.m8n8.x4.shared.b16 {%0,%1,%2,%3}, [%4];"
                             : "=r"(a0), "=r"(a1), "=r"(a2), "=r"(a3)
                             : "r"(abase + (uint32_t)(rt*16*YROWB) + ks*32));
                #pragma unroll
                for (int pp = 0; pp < 4; pp++) {
                    MMA_F16(acc[rt][2*pp+0], a0, a1, a2, a3, bf[pp].x, bf[pp].y);
                    MMA_F16(acc[rt][2*pp+1], a0, a1, a2, a3, bf[pp].z, bf[pp].w);
                }
            }
        }

        // ---- row 128 of next tile (x1 of its row 127), 32 parallel LDGs
        if (has_next && tid < 32) {
            int rg7 = ntile*TM + 127;
            int b7 = rg7 / 1023, s7 = rg7 - b7*1023;
            float4 v = *((const float4*)(x + (size_t)(b7*SS + s7 + 1)*H) + tid);
            __half2 p0 = __floats2half2_rn(v.x, v.y);
            __half2 p1 = __floats2half2_rn(v.z, v.w);
            uint2 u; u.x = *(uint32_t*)&p0; u.y = *(uint32_t*)&p1;
            *(uint2*)(ynxt + (size_t)128*YROWB + tid*8) = u;
        }

        // ---- epilogue: d = y + P - x1, y/x1 fp16 from smem rows r / r+1
        float lsum = 0.f;
        #pragma unroll
        for (int rt = 0; rt < 2; rt++) {
            #pragma unroll
            for (int rr = 0; rr < 2; rr++) {
                int r  = rb + rt*16 + rr*8 + (lane >> 2);
                int rg = tile*TM + r;
                int b  = rg / 1023;
                int s  = rg - b*1023;
                const char* yrow  = ycur + (size_t)r*YROWB + (lane & 3)*4;
                const char* x1row = yrow + YROWB;
                bool bnd = (s == 1022);
                const float* gx1 = x + (size_t)(b*SS + s + 1)*H;
                #pragma unroll
                for (int t = 0; t < 8; t++) {
                    float2 yf = __half22float2(*(const __half2*)(yrow + (cb + t)*16));
                    float2 xf;
                    if (bnd) {
                        xf = *(const float2*)(gx1 + (cb + t)*8 + (lane & 3)*2);
                    } else {
                        xf = __half22float2(*(const __half2*)(x1row + (cb + t)*16));
                    }
                    float d;
                    d = yf.x + acc[rt][t][rr*2+0] - xf.x; lsum = fmaf(d, d, lsum);
                    d = yf.y + acc[rt][t][rr*2+1] - xf.y; lsum = fmaf(d, d, lsum);
                }
            }
        }
        csum += (double)lsum;

        __syncthreads();      // ycur reads + ynxt writes complete
        buf ^= 1;
    }

    // ================= final reduction (fixed order -> deterministic)
    #pragma unroll
    for (int off = 16; off; off >>= 1)
        csum += __shfl_down_sync(0xffffffffu, csum, off);
    __shared__ double redd[8];
    if (lane == 0) redd[w] = csum;
    __syncthreads();

    __shared__ bool is_last;
    if (tid == 0) {
        double s = 0.0;
        #pragma unroll
        for (int q = 0; q < 8; q++) s += redd[q];
        g_partials[cta] = s;
        __threadfence();
        unsigned int old = atomicAdd(&g_done, 1u);
        is_last = (old == (unsigned int)(NCTA - 1));
    }
    __syncthreads();

    if (is_last) {
        double s = (tid < NCTA) ? g_partials[tid] : 0.0;
        if (tid + 256 < NCTA) s += g_partials[tid + 256];
        __shared__ double sd[256];
        sd[tid] = s; __syncthreads();
        for (int off = 128; off; off >>= 1) {
            if (tid < off) sd[tid] += sd[tid + off];
            __syncthreads();
        }
        if (tid == 0) {
            double step_loss = sd[0] / ((double)ROWS * (double)H);
            double l2_loss   = g_l2 / ((double)H * (double)H);
            out[0] = (float)(step_loss + 0.001 * l2_loss);
            g_done = 0u; g_barA = 0u; g_barB = 0u;   // reset for graph replay
        }
    }
}

// ---------------------------------------------------------------- launch
extern "C" void kernel_launch(void* const* d_in, const int* in_sizes, int n_in,
                              void* d_out, int out_size) {
    const float* x     = (const float*)d_in[0];
    const float* coeff = (const float*)d_in[1];
    if (n_in >= 2 && in_sizes[0] == H*H) {
        coeff = (const float*)d_in[0];
        x     = (const float*)d_in[1];
    }
    float* out = (float*)d_out;

    cudaFuncSetAttribute(fused_kernel,
                         cudaFuncAttributeMaxDynamicSharedMemorySize, SMEM_TOTAL);

    fused_kernel<<<NCTA, 256, SMEM_TOTAL>>>(x, coeff, out);
}

// round 16
// speedup vs baseline: 1.0456x; 1.0406x over previous
#include <cuda_runtime.h>
#include <cuda_fp16.h>
#include <cstdint>

// ---------------------------------------------------------------- constants
#define H 128
#define BB 256
#define SS 1024
#define ROWS (BB*(SS-1))          // 261888
#define TM 128                    // rows per tile
#define NTILES (ROWS/TM)          // 2046 (exact)
#define NCTA 296                  // persistent CTAs (2/SM x 148, all resident)

#define YSTR 136                  // fp16 elems per y-tile row (272 B, padded)
#define YROWB (YSTR*2)            // 272
#define YTILE (129*YROWB)         // 35088 (129 rows: +1 for x1 of row 127)

// dynamic smem layout (bytes)
#define SM_DF   0                         // D fp16 B-frags (paired), 32768
#define SM_Y0   32768
#define SM_Y1   (SM_Y0 + YTILE)
#define SMEM_TOTAL (SM_Y1 + YTILE)        // 102944 -> 2 CTAs/SM

// ---------------------------------------------------------------- scratch
__device__ float          g_B[H*H];          // C^2
__device__ __half         g_Dfrag[H*H];      // D fp16, paired B-frag order
__device__ double         g_partials[NCTA];
__device__ double         g_l2row[H];
__device__ double         g_l2;
__device__ unsigned int   g_done;
__device__ unsigned int   g_barA;            // prep phase barrier (128)
__device__ unsigned int   g_barB;            // all-CTA barrier (296)

// ---------------------------------------------------------------- helpers
__device__ __forceinline__ uint32_t smem_u32(const void* p) {
    uint32_t a;
    asm("{ .reg .u64 t; cvta.to.shared.u64 t, %1; cvt.u32.u64 %0, t; }"
        : "=r"(a) : "l"(p));
    return a;
}

#define MMA_F16(ACC, A0, A1, A2, A3, B0, B1)                                \
    asm volatile(                                                           \
        "mma.sync.aligned.m16n8k16.row.col.f32.f16.f16.f32 "                \
        "{%0,%1,%2,%3}, {%4,%5,%6,%7}, {%8,%9}, {%0,%1,%2,%3};"             \
        : "+f"((ACC)[0]), "+f"((ACC)[1]), "+f"((ACC)[2]), "+f"((ACC)[3])    \
        : "r"(A0), "r"(A1), "r"(A2), "r"(A3), "r"(B0), "r"(B1))

__device__ __forceinline__ void cvt_store16(char* dst, float4 v0, float4 v1) {
    __half2 p0 = __floats2half2_rn(v0.x, v0.y);
    __half2 p1 = __floats2half2_rn(v0.z, v0.w);
    __half2 p2 = __floats2half2_rn(v1.x, v1.y);
    __half2 p3 = __floats2half2_rn(v1.z, v1.w);
    uint4 u;
    u.x = *(uint32_t*)&p0; u.y = *(uint32_t*)&p1;
    u.z = *(uint32_t*)&p2; u.w = *(uint32_t*)&p3;
    *(uint4*)dst = u;
}

// ---------------------------------------------------------------- fused kernel
// 296 CTAs x 256 threads, 2 CTAs/SM (all co-resident -> global barriers OK).
// Stage 0: every CTA converts its first tile. Stage 1: CTAs 0..127 compute
// M = I + D (two phases, barrier-A). Stage 2: barrier-B, stage D, persistent
// mainloop with convert pipelined inside the mma loop. Final: fused reduction.
__global__ void __launch_bounds__(256, 2)
fused_kernel(const float* __restrict__ x, const float* __restrict__ coeff,
             float* __restrict__ out) {
    extern __shared__ char smem[];
    const int tid = threadIdx.x;
    const int cta = blockIdx.x;

    // ================= stage 0: convert first tile -> SM_Y0 (no D needed)
    {
        int row = tid >> 1, half = tid & 1;
        int rg = cta*TM + row;
        int b = rg / 1023, s = rg - b*1023;
        const float4* src = (const float4*)(x + (size_t)(b*SS + s)*H) + half*16;
        char* dst = smem + SM_Y0 + (size_t)row*YROWB + half*128;
        #pragma unroll
        for (int q = 0; q < 8; q++)
            cvt_store16(dst + q*16, src[2*q], src[2*q + 1]);
        if (tid < 32) {   // row 128 = x1 of row 127 (32 parallel LDGs)
            int rg7 = cta*TM + 127;
            int b7 = rg7 / 1023, s7 = rg7 - b7*1023;
            float4 v = *((const float4*)(x + (size_t)(b7*SS + s7 + 1)*H) + tid);
            __half2 p0 = __floats2half2_rn(v.x, v.y);
            __half2 p1 = __floats2half2_rn(v.z, v.w);
            uint2 u; u.x = *(uint32_t*)&p0; u.y = *(uint32_t*)&p1;
            *(uint2*)(smem + SM_Y0 + (size_t)128*YROWB + tid*8) = u;
        }
    }

    // ================= stage 1: prep (CTAs 0..127), smem overlaid on SM_Y1
    if (cta < H) {
        float* crow  = (float*)(smem + SM_Y1);
        float* brow  = crow + H;
        float* c2row = brow + H;
        float* part  = c2row + H;          // [2][H]
        const int i  = cta;
        const int j  = tid & 127;
        const int kh = tid >> 7;           // 0/1: k-half

        if (tid < H) crow[tid] = coeff[i*H + tid];
        __syncthreads();

        {   // phase 1: B[i][j] = sum_k crow[k] * C[k][j]
            float a0=0.f, a1=0.f, a2=0.f, a3=0.f;
            int k0 = kh * 64;
            #pragma unroll
            for (int k = 0; k < 64; k += 4) {
                a0 = fmaf(crow[k0+k],   __ldg(coeff + (k0+k)*H + j),   a0);
                a1 = fmaf(crow[k0+k+1], __ldg(coeff + (k0+k+1)*H + j), a1);
                a2 = fmaf(crow[k0+k+2], __ldg(coeff + (k0+k+2)*H + j), a2);
                a3 = fmaf(crow[k0+k+3], __ldg(coeff + (k0+k+3)*H + j), a3);
            }
            part[kh*H + j] = (a0+a1) + (a2+a3);
        }
        __syncthreads();
        if (tid < H) {
            float b = part[tid] + part[H + tid];
            g_B[i*H + tid] = b;
            brow[tid]  = b;
            c2row[tid] = crow[tid]*(1.0f/6.0f) + b*(1.0f/24.0f);
        }
        {   // per-row l2 partial
            float v = 0.f;
            if (tid < H) { float c = crow[tid], cc = c*c; v = cc*cc; }
            #pragma unroll
            for (int off = 16; off; off >>= 1)
                v += __shfl_down_sync(0xffffffffu, v, off);
            __shared__ float lred[8];
            if ((tid & 31) == 0) lred[tid >> 5] = v;
            __syncthreads();
            if (tid == 0) {
                float s = 0.f;
                #pragma unroll
                for (int q = 0; q < 8; q++) s += lred[q];
                g_l2row[i] = (double)s;
            }
        }

        // barrier-A over the 128 prep CTAs
        __threadfence();
        __syncthreads();
        if (tid == 0) {
            atomicAdd(&g_barA, 1u);
            while (*(volatile unsigned int*)&g_barA < (unsigned int)H) { }
        }
        __syncthreads();
        __threadfence();

        {   // phase 2: D[i][j] = crow + B/2 + c2row @ B
            float a0=0.f, a1=0.f, a2=0.f, a3=0.f;
            int k0 = kh * 64;
            #pragma unroll
            for (int k = 0; k < 64; k += 4) {
                a0 = fmaf(c2row[k0+k],   __ldg(g_B + (k0+k)*H + j),   a0);
                a1 = fmaf(c2row[k0+k+1], __ldg(g_B + (k0+k+1)*H + j), a1);
                a2 = fmaf(c2row[k0+k+2], __ldg(g_B + (k0+k+2)*H + j), a2);
                a3 = fmaf(c2row[k0+k+3], __ldg(g_B + (k0+k+3)*H + j), a3);
            }
            part[kh*H + j] = (a0+a1) + (a2+a3);
        }
        __syncthreads();
        if (tid < H) {
            float d = crow[tid] + 0.5f*brow[tid] + (part[tid] + part[H + tid]);
            // paired m16n8k16 B-frag scatter (i = n, tid = k)
            int ks = tid >> 4, kin = tid & 15;
            int reg = kin >> 3;
            int lane = ((i & 7) << 2) + ((kin & 7) >> 1);
            int fidx = (((ks*8 + (i >> 4))*32 + lane) << 3)
                     + (((i >> 3) & 1) << 2) + (reg << 1) + (tid & 1);
            g_Dfrag[fidx] = __float2half_rn(d);
        }
        if (i == 0 && tid == 0) {
            double s = 0.0;
            #pragma unroll
            for (int r = 0; r < H; r++) s += g_l2row[r];
            g_l2 = s;
        }
    }

    // ================= stage 2: barrier-B over ALL 296 CTAs
    __threadfence();
    __syncthreads();
    if (tid == 0) {
        atomicAdd(&g_barB, 1u);
        while (*(volatile unsigned int*)&g_barB < (unsigned int)NCTA) { }
    }
    __syncthreads();
    __threadfence();

    // ---- stage D B-fragments once, 32KB
    {
        const uint4* df = (const uint4*)g_Dfrag;
        uint4* sh = (uint4*)(smem + SM_DF);
        #pragma unroll
        for (int q = 0; q < 8; q++) sh[tid + q*256] = df[tid + q*256];
    }
    __syncthreads();          // also publishes stage-0 tile0 converts

    // ================= persistent mainloop
    const int w    = tid >> 5;
    const int lane = tid & 31;
    const int rb   = (w & 3) * 32;
    const int cb   = (w >> 2) * 8;
    const int pb   = cb >> 1;
    const int vrow = tid >> 1, vhalf = tid & 1;    // convert mapping

    double csum = 0.0;
    int buf = 0;

    for (int tile = cta; tile < NTILES; tile += NCTA) {
        char* ycur = smem + (buf ? SM_Y1 : SM_Y0);
        char* ynxt = smem + (buf ? SM_Y0 : SM_Y1);

        const int ntile = tile + NCTA;
        const bool has_next = (ntile < NTILES);
        const float4* nsrc = (const float4*)x;
        char* ndst = ynxt + (size_t)vrow*YROWB + vhalf*128;
        if (has_next) {
            int rg = ntile*TM + vrow;
            int b = rg / 1023, s = rg - b*1023;
            nsrc = (const float4*)(x + (size_t)(b*SS + s)*H) + vhalf*16;
        }

        float acc[2][8][4];
        #pragma unroll
        for (int rt = 0; rt < 2; rt++)
            #pragma unroll
            for (int t = 0; t < 8; t++) {
                acc[rt][t][0] = 0.f; acc[rt][t][1] = 0.f;
                acc[rt][t][2] = 0.f; acc[rt][t][3] = 0.f;
            }
        const uint32_t abase = smem_u32(ycur)
            + (uint32_t)((rb + (lane & 15))*YSTR + (lane >> 4)*8)*2;

        // ---- mma loop with pipelined next-tile convert (1-chunk lookahead)
        // All smem loads (2x ldmatrix + 4x LDS.128) hoisted ahead of the MMAs
        // to maximize LDS->HMMA distance.
        float4 pf0, pf1;
        if (has_next) { pf0 = nsrc[0]; pf1 = nsrc[1]; }

        #pragma unroll
        for (int ks = 0; ks < 8; ks++) {
            float4 nf0, nf1;
            if (has_next && ks < 7) { nf0 = nsrc[2*ks+2]; nf1 = nsrc[2*ks+3]; }

            uint32_t a0[2], a1[2], a2[2], a3[2];
            #pragma unroll
            for (int rt = 0; rt < 2; rt++) {
                asm volatile("ldmatrix.sync.aligned.m8n8.x4.shared.b16 {%0,%1,%2,%3}, [%4];"
                             : "=r"(a0[rt]), "=r"(a1[rt]), "=r"(a2[rt]), "=r"(a3[rt])
                             : "r"(abase + (uint32_t)(rt*16*YROWB) + ks*32));
            }
            uint4 bf[4];
            #pragma unroll
            for (int pp = 0; pp < 4; pp++) {
                uint32_t foff = (uint32_t)(((ks*8 + pb + pp)*32 + lane) * 16);
                bf[pp] = *(const uint4*)(smem + SM_DF + foff);
            }
            #pragma unroll
            for (int rt = 0; rt < 2; rt++) {
                #pragma unroll
                for (int pp = 0; pp < 4; pp++) {
                    MMA_F16(acc[rt][2*pp+0], a0[rt], a1[rt], a2[rt], a3[rt],
                            bf[pp].x, bf[pp].y);
                    MMA_F16(acc[rt][2*pp+1], a0[rt], a1[rt], a2[rt], a3[rt],
                            bf[pp].z, bf[pp].w);
                }
            }
            if (has_next) cvt_store16(ndst + ks*16, pf0, pf1);
            if (ks < 7) { pf0 = nf0; pf1 = nf1; }
        }

        // ---- row 128 of next tile (x1 of its row 127), 32 parallel LDGs
        if (has_next && tid < 32) {
            int rg7 = ntile*TM + 127;
            int b7 = rg7 / 1023, s7 = rg7 - b7*1023;
            float4 v = *((const float4*)(x + (size_t)(b7*SS + s7 + 1)*H) + tid);
            __half2 p0 = __floats2half2_rn(v.x, v.y);
            __half2 p1 = __floats2half2_rn(v.z, v.w);
            uint2 u; u.x = *(uint32_t*)&p0; u.y = *(uint32_t*)&p1;
            *(uint2*)(ynxt + (size_t)128*YROWB + tid*8) = u;
        }

        // ---- epilogue: d = y + P - x1, y/x1 fp16 from smem rows r / r+1
        float lsum = 0.f;
        #pragma unroll
        for (int rt = 0; rt < 2; rt++) {
            #pragma unroll
            for (int rr = 0; rr < 2; rr++) {
                int r  = rb + rt*16 + rr*8 + (lane >> 2);
                int rg = tile*TM + r;
                int b  = rg / 1023;
                int s  = rg - b*1023;
                const char* yrow  = ycur + (size_t)r*YROWB + (lane & 3)*4;
                const char* x1row = yrow + YROWB;
                const bool bnd = (s == 1022);
                const float* gx1 = x + (size_t)(b*SS + s + 1)*H + (lane & 3)*2;
                #pragma unroll
                for (int t = 0; t < 8; t++) {
                    float2 yf = __half22float2(*(const __half2*)(yrow + (cb + t)*16));
                    float2 xf;
                    if (bnd) {
                        xf = *(const float2*)(gx1 + (cb + t)*8);
                    } else {
                        xf = __half22float2(*(const __half2*)(x1row + (cb + t)*16));
                    }
                    float d;
                    d = yf.x + acc[rt][t][rr*2+0] - xf.x; lsum = fmaf(d, d, lsum);
                    d = yf.y + acc[rt][t][rr*2+1] - xf.y; lsum = fmaf(d, d, lsum);
                }
            }
        }
        csum += (double)lsum;

        __syncthreads();      // ycur reads + ynxt writes complete
        buf ^= 1;
    }

    // ================= final reduction (fixed order -> deterministic)
    #pragma unroll
    for (int off = 16; off; off >>= 1)
        csum += __shfl_down_sync(0xffffffffu, csum, off);
    __shared__ double redd[8];
    if (lane == 0) redd[w] = csum;
    __syncthreads();

    __shared__ bool is_last;
    if (tid == 0) {
        double s = 0.0;
        #pragma unroll
        for (int q = 0; q < 8; q++) s += redd[q];
        g_partials[cta] = s;
        __threadfence();
        unsigned int old = atomicAdd(&g_done, 1u);
        is_last = (old == (unsigned int)(NCTA - 1));
    }
    __syncthreads();

    if (is_last) {
        double s = (tid < NCTA) ? g_partials[tid] : 0.0;
        if (tid + 256 < NCTA) s += g_partials[tid + 256];
        __shared__ double sd[256];
        sd[tid] = s; __syncthreads();
        for (int off = 128; off; off >>= 1) {
            if (tid < off) sd[tid] += sd[tid + off];
            __syncthreads();
        }
        if (tid == 0) {
            double step_loss = sd[0] / ((double)ROWS * (double)H);
            double l2_loss   = g_l2 / ((double)H * (double)H);
            out[0] = (float)(step_loss + 0.001 * l2_loss);
            g_done = 0u; g_barA = 0u; g_barB = 0u;   // reset for graph replay
        }
    }
}

// ---------------------------------------------------------------- launch
extern "C" void kernel_launch(void* const* d_in, const int* in_sizes, int n_in,
                              void* d_out, int out_size) {
    const float* x     = (const float*)d_in[0];
    const float* coeff = (const float*)d_in[1];
    if (n_in >= 2 && in_sizes[0] == H*H) {
        coeff = (const float*)d_in[0];
        x     = (const float*)d_in[1];
    }
    float* out = (float*)d_out;

    cudaFuncSetAttribute(fused_kernel,
                         cudaFuncAttributeMaxDynamicSharedMemorySize, SMEM_TOTAL);

    fused_kernel<<<NCTA, 256, SMEM_TOTAL>>>(x, coeff, out);
}

// round 17
// speedup vs baseline: 1.1751x; 1.1239x over previous
#include <cuda_runtime.h>
#include <cuda_fp16.h>
#include <cstdint>

// ---------------------------------------------------------------- constants
#define H 128
#define BB 256
#define SS 1024
#define ROWS (BB*(SS-1))          // 261888
#define TM 128                    // rows per tile
#define NTILES (ROWS/TM)          // 2046 (exact)
#define NCTA 296                  // persistent CTAs (2/SM x 148, all resident)

#define YSTR 136                  // fp16 elems per y-tile row (272 B, padded)
#define YROWB (YSTR*2)            // 272
#define YTILE (129*YROWB)         // 35088 (129 rows: +1 for x1 of row 127)

#define SROWB 528                 // stage fp32 row stride (33x16B; LDS-conflict-free)
#define STAGE_BYTES (33*SROWB)    // 17424 (33 rows: 32 + spare for row128)

// dynamic smem layout (bytes)
#define SM_DF   0                         // D fp16 B-frags (paired), 32768
#define SM_Y    32768                     // single fp16 y tile, 35088
#define SM_S0   (SM_Y + YTILE)            // fp32 stage 0
#define SM_S1   (SM_S0 + STAGE_BYTES)     // fp32 stage 1
#define SMEM_TOTAL (SM_S1 + STAGE_BYTES)  // 102704 -> 2 CTAs/SM

// ---------------------------------------------------------------- scratch
__device__ float          g_B[H*H];          // C^2
__device__ __half         g_Dfrag[H*H];      // D fp16, paired B-frag order
__device__ double         g_partials[NCTA];
__device__ double         g_l2row[H];
__device__ double         g_l2;
__device__ unsigned int   g_done;
__device__ unsigned int   g_barA;            // prep phase barrier (128)
__device__ unsigned int   g_barB;            // all-CTA barrier (296)

// ---------------------------------------------------------------- helpers
__device__ __forceinline__ uint32_t smem_u32(const void* p) {
    uint32_t a;
    asm("{ .reg .u64 t; cvta.to.shared.u64 t, %1; cvt.u32.u64 %0, t; }"
        : "=r"(a) : "l"(p));
    return a;
}

#define MMA_F16(ACC, A0, A1, A2, A3, B0, B1)                                \
    asm volatile(                                                           \
        "mma.sync.aligned.m16n8k16.row.col.f32.f16.f16.f32 "                \
        "{%0,%1,%2,%3}, {%4,%5,%6,%7}, {%8,%9}, {%0,%1,%2,%3};"             \
        : "+f"((ACC)[0]), "+f"((ACC)[1]), "+f"((ACC)[2]), "+f"((ACC)[3])    \
        : "r"(A0), "r"(A1), "r"(A2), "r"(A3), "r"(B0), "r"(B1))

__device__ __forceinline__ void cp16(uint32_t dst, const void* src) {
    asm volatile("cp.async.cg.shared.global [%0], [%1], 16;"
                 :: "r"(dst), "l"(src));
}
#define CP_COMMIT() asm volatile("cp.async.commit_group;" ::: "memory")
#define CP_WAIT(N)  asm volatile("cp.async.wait_group %0;" :: "n"(N) : "memory")

__device__ __forceinline__ void cvt_store16(char* dst, float4 v0, float4 v1) {
    __half2 p0 = __floats2half2_rn(v0.x, v0.y);
    __half2 p1 = __floats2half2_rn(v0.z, v0.w);
    __half2 p2 = __floats2half2_rn(v1.x, v1.y);
    __half2 p3 = __floats2half2_rn(v1.z, v1.w);
    uint4 u;
    u.x = *(uint32_t*)&p0; u.y = *(uint32_t*)&p1;
    u.z = *(uint32_t*)&p2; u.w = *(uint32_t*)&p3;
    *(uint4*)dst = u;
}

// ---------------------------------------------------------------- fused kernel
// 296 CTAs x 256 threads, 2 CTAs/SM (all co-resident -> global barriers OK).
// Stage 0: every CTA converts its first tile (direct LDG; hidden behind prep).
// Stage 1: CTAs 0..127 compute M = I + D (barrier-A). Stage 2: barrier-B,
// stage D frags. Mainloop: cp.async-staged fp32 chunks -> fp16 convert,
// pure smem+HMMA inner loop. Final: fused deterministic reduction.
__global__ void __launch_bounds__(256, 2)
fused_kernel(const float* __restrict__ x, const float* __restrict__ coeff,
             float* __restrict__ out) {
    extern __shared__ char smem[];
    const uint32_t sbase = smem_u32(smem);
    const int tid = threadIdx.x;
    const int cta = blockIdx.x;

    // ================= stage 0: convert first tile -> SM_Y (direct LDG)
    {
        int row = tid >> 1, half = tid & 1;
        int rg = cta*TM + row;
        int b = rg / 1023, s = rg - b*1023;
        const float4* src = (const float4*)(x + (size_t)(b*SS + s)*H) + half*16;
        char* dst = smem + SM_Y + (size_t)row*YROWB + half*128;
        #pragma unroll
        for (int q = 0; q < 8; q++)
            cvt_store16(dst + q*16, src[2*q], src[2*q + 1]);
        if (tid < 32) {   // row 128 = x1 of row 127
            int rg7 = cta*TM + 127;
            int b7 = rg7 / 1023, s7 = rg7 - b7*1023;
            float4 v = *((const float4*)(x + (size_t)(b7*SS + s7 + 1)*H) + tid);
            __half2 p0 = __floats2half2_rn(v.x, v.y);
            __half2 p1 = __floats2half2_rn(v.z, v.w);
            uint2 u; u.x = *(uint32_t*)&p0; u.y = *(uint32_t*)&p1;
            *(uint2*)(smem + SM_Y + (size_t)128*YROWB + tid*8) = u;
        }
    }

    // ================= stage 1: prep (CTAs 0..127), smem overlaid on stages
    if (cta < H) {
        float* crow  = (float*)(smem + SM_S0);
        float* brow  = crow + H;
        float* c2row = brow + H;
        float* part  = c2row + H;          // [2][H]
        const int i  = cta;
        const int j  = tid & 127;
        const int kh = tid >> 7;           // 0/1: k-half

        if (tid < H) crow[tid] = coeff[i*H + tid];
        __syncthreads();

        {   // phase 1: B[i][j] = sum_k crow[k] * C[k][j]
            float a0=0.f, a1=0.f, a2=0.f, a3=0.f;
            int k0 = kh * 64;
            #pragma unroll
            for (int k = 0; k < 64; k += 4) {
                a0 = fmaf(crow[k0+k],   __ldg(coeff + (k0+k)*H + j),   a0);
                a1 = fmaf(crow[k0+k+1], __ldg(coeff + (k0+k+1)*H + j), a1);
                a2 = fmaf(crow[k0+k+2], __ldg(coeff + (k0+k+2)*H + j), a2);
                a3 = fmaf(crow[k0+k+3], __ldg(coeff + (k0+k+3)*H + j), a3);
            }
            part[kh*H + j] = (a0+a1) + (a2+a3);
        }
        __syncthreads();
        if (tid < H) {
            float b = part[tid] + part[H + tid];
            g_B[i*H + tid] = b;
            brow[tid]  = b;
            c2row[tid] = crow[tid]*(1.0f/6.0f) + b*(1.0f/24.0f);
        }
        {   // per-row l2 partial
            float v = 0.f;
            if (tid < H) { float c = crow[tid], cc = c*c; v = cc*cc; }
            #pragma unroll
            for (int off = 16; off; off >>= 1)
                v += __shfl_down_sync(0xffffffffu, v, off);
            __shared__ float lred[8];
            if ((tid & 31) == 0) lred[tid >> 5] = v;
            __syncthreads();
            if (tid == 0) {
                float s = 0.f;
                #pragma unroll
                for (int q = 0; q < 8; q++) s += lred[q];
                g_l2row[i] = (double)s;
            }
        }

        // barrier-A over the 128 prep CTAs
        __threadfence();
        __syncthreads();
        if (tid == 0) {
            atomicAdd(&g_barA, 1u);
            while (*(volatile unsigned int*)&g_barA < (unsigned int)H) { }
        }
        __syncthreads();
        __threadfence();

        {   // phase 2: D[i][j] = crow + B/2 + c2row @ B
            float a0=0.f, a1=0.f, a2=0.f, a3=0.f;
            int k0 = kh * 64;
            #pragma unroll
            for (int k = 0; k < 64; k += 4) {
                a0 = fmaf(c2row[k0+k],   __ldg(g_B + (k0+k)*H + j),   a0);
                a1 = fmaf(c2row[k0+k+1], __ldg(g_B + (k0+k+1)*H + j), a1);
                a2 = fmaf(c2row[k0+k+2], __ldg(g_B + (k0+k+2)*H + j), a2);
                a3 = fmaf(c2row[k0+k+3], __ldg(g_B + (k0+k+3)*H + j), a3);
            }
            part[kh*H + j] = (a0+a1) + (a2+a3);
        }
        __syncthreads();
        if (tid < H) {
            float d = crow[tid] + 0.5f*brow[tid] + (part[tid] + part[H + tid]);
            // paired m16n8k16 B-frag scatter (i = n, tid = k)
            int ks = tid >> 4, kin = tid & 15;
            int reg = kin >> 3;
            int lane = ((i & 7) << 2) + ((kin & 7) >> 1);
            int fidx = (((ks*8 + (i >> 4))*32 + lane) << 3)
                     + (((i >> 3) & 1) << 2) + (reg << 1) + (tid & 1);
            g_Dfrag[fidx] = __float2half_rn(d);
        }
        if (i == 0 && tid == 0) {
            double s = 0.0;
            #pragma unroll
            for (int r = 0; r < H; r++) s += g_l2row[r];
            g_l2 = s;
        }
    }

    // ================= stage 2: barrier-B over ALL 296 CTAs
    __threadfence();
    __syncthreads();
    if (tid == 0) {
        atomicAdd(&g_barB, 1u);
        while (*(volatile unsigned int*)&g_barB < (unsigned int)NCTA) { }
    }
    __syncthreads();
    __threadfence();

    // ---- stage D B-fragments once, 32KB
    {
        const uint4* df = (const uint4*)g_Dfrag;
        uint4* sh = (uint4*)(smem + SM_DF);
        #pragma unroll
        for (int q = 0; q < 8; q++) sh[tid + q*256] = df[tid + q*256];
    }
    __syncthreads();          // also publishes stage-0 tile0 converts

    // ================= persistent mainloop
    const int w    = tid >> 5;
    const int lane = tid & 31;
    const int rb   = (w & 3) * 32;
    const int cb   = (w >> 2) * 8;
    const int pb   = cb >> 1;
    const int srow = tid >> 3, seg = tid & 7;   // staging mapping (32 rows x 8)

    const uint32_t abase0 = sbase + SM_Y;
    const uint32_t s0 = sbase + SM_S0, s1 = sbase + SM_S1;

    double csum = 0.0;

    for (int tile = cta; tile < NTILES; tile += NCTA) {
        const int ntile = tile + NCTA;
        const bool has_next = (ntile < NTILES);

        // ---- issue g0 (rows 0-31) -> stage0, g1 (rows 32-63) -> stage1
        if (has_next) {
            #pragma unroll
            for (int c = 0; c < 2; c++) {
                int rg = ntile*TM + c*32 + srow;
                int b = rg / 1023, s = rg - b*1023;
                const char* src = (const char*)(x + (size_t)(b*SS + s)*H) + seg*64;
                uint32_t dst = (c ? s1 : s0) + (uint32_t)(srow*SROWB + seg*64);
                cp16(dst,      src);
                cp16(dst + 16, src + 16);
                cp16(dst + 32, src + 32);
                cp16(dst + 48, src + 48);
                CP_COMMIT();
            }
        }

        // ---- HMMA mainloop (pure smem: ldmatrix + LDS.128 + HMMA)
        float acc[2][8][4];
        #pragma unroll
        for (int rt = 0; rt < 2; rt++)
            #pragma unroll
            for (int t = 0; t < 8; t++) {
                acc[rt][t][0] = 0.f; acc[rt][t][1] = 0.f;
                acc[rt][t][2] = 0.f; acc[rt][t][3] = 0.f;
            }
        const uint32_t abase = abase0
            + (uint32_t)((rb + (lane & 15))*YSTR + (lane >> 4)*8)*2;

        #pragma unroll
        for (int ks = 0; ks < 8; ks++) {
            uint32_t a0[2], a1[2], a2[2], a3[2];
            #pragma unroll
            for (int rt = 0; rt < 2; rt++) {
                asm volatile("ldmatrix.sync.aligned.m8n8.x4.shared.b16 {%0,%1,%2,%3}, [%4];"
                             : "=r"(a0[rt]), "=r"(a1[rt]), "=r"(a2[rt]), "=r"(a3[rt])
                             : "r"(abase + (uint32_t)(rt*16*YROWB) + ks*32));
            }
            uint4 bf[4];
            #pragma unroll
            for (int pp = 0; pp < 4; pp++) {
                uint32_t foff = (uint32_t)(((ks*8 + pb + pp)*32 + lane) * 16);
                bf[pp] = *(const uint4*)(smem + SM_DF + foff);
            }
            #pragma unroll
            for (int rt = 0; rt < 2; rt++) {
                #pragma unroll
                for (int pp = 0; pp < 4; pp++) {
                    MMA_F16(acc[rt][2*pp+0], a0[rt], a1[rt], a2[rt], a3[rt],
                            bf[pp].x, bf[pp].y);
                    MMA_F16(acc[rt][2*pp+1], a0[rt], a1[rt], a2[rt], a3[rt],
                            bf[pp].z, bf[pp].w);
                }
            }
        }

        // ---- epilogue: d = y + P - x1, y/x1 fp16 from smem rows r / r+1
        float lsum = 0.f;
        #pragma unroll
        for (int rt = 0; rt < 2; rt++) {
            #pragma unroll
            for (int rr = 0; rr < 2; rr++) {
                int r  = rb + rt*16 + rr*8 + (lane >> 2);
                int rg = tile*TM + r;
                int b  = rg / 1023;
                int s  = rg - b*1023;
                const char* yrow  = smem + SM_Y + (size_t)r*YROWB + (lane & 3)*4;
                const char* x1row = yrow + YROWB;
                const bool bnd = (s == 1022);
                const float* gx1 = x + (size_t)(b*SS + s + 1)*H + (lane & 3)*2;
                #pragma unroll
                for (int t = 0; t < 8; t++) {
                    float2 yf = __half22float2(*(const __half2*)(yrow + (cb + t)*16));
                    float2 xf;
                    if (bnd) {
                        xf = *(const float2*)(gx1 + (cb + t)*8);
                    } else {
                        xf = __half22float2(*(const __half2*)(x1row + (cb + t)*16));
                    }
                    float d;
                    d = yf.x + acc[rt][t][rr*2+0] - xf.x; lsum = fmaf(d, d, lsum);
                    d = yf.y + acc[rt][t][rr*2+1] - xf.y; lsum = fmaf(d, d, lsum);
                }
            }
        }
        csum += (double)lsum;

        __syncthreads();      // all Y reads done; Y may be overwritten now

        // ---- staged convert of next tile into Y (rolling cp.async pipeline)
        if (has_next) {
            char* ydst = smem + SM_Y + (size_t)srow*YROWB + seg*32;
            const char* sp0 = smem + SM_S0 + (size_t)srow*SROWB + seg*64;
            const char* sp1 = smem + SM_S1 + (size_t)srow*SROWB + seg*64;

            // g0 -> Y rows 0-31 ; issue g2 (rows 64-95) -> stage0
            CP_WAIT(1);
            {
                float4 v0 = *(const float4*)(sp0);
                float4 v1 = *(const float4*)(sp0 + 16);
                float4 v2 = *(const float4*)(sp0 + 32);
                float4 v3 = *(const float4*)(sp0 + 48);
                cvt_store16(ydst,      v0, v1);
                cvt_store16(ydst + 16, v2, v3);
            }
            {
                int rg = ntile*TM + 64 + srow;
                int b = rg / 1023, s = rg - b*1023;
                const char* src = (const char*)(x + (size_t)(b*SS + s)*H) + seg*64;
                uint32_t dst = s0 + (uint32_t)(srow*SROWB + seg*64);
                cp16(dst, src); cp16(dst+16, src+16);
                cp16(dst+32, src+32); cp16(dst+48, src+48);
                CP_COMMIT();
            }
            // g1 -> Y rows 32-63 ; issue g3 (rows 96-127 + row128) -> stage1
            CP_WAIT(1);
            {
                float4 v0 = *(const float4*)(sp1);
                float4 v1 = *(const float4*)(sp1 + 16);
                float4 v2 = *(const float4*)(sp1 + 32);
                float4 v3 = *(const float4*)(sp1 + 48);
                char* yd = ydst + (size_t)32*YROWB;
                cvt_store16(yd,      v0, v1);
                cvt_store16(yd + 16, v2, v3);
            }
            {
                int rg = ntile*TM + 96 + srow;
                int b = rg / 1023, s = rg - b*1023;
                const char* src = (const char*)(x + (size_t)(b*SS + s)*H) + seg*64;
                uint32_t dst = s1 + (uint32_t)(srow*SROWB + seg*64);
                cp16(dst, src); cp16(dst+16, src+16);
                cp16(dst+32, src+32); cp16(dst+48, src+48);
                if (tid < 8) {   // row 128 = x1 of next tile's row 127
                    int rg7 = ntile*TM + 127;
                    int b7 = rg7 / 1023, s7 = rg7 - b7*1023;
                    const char* s8 = (const char*)(x + (size_t)(b7*SS + s7 + 1)*H) + tid*64;
                    uint32_t d8 = s1 + (uint32_t)(32*SROWB + tid*64);
                    cp16(d8, s8); cp16(d8+16, s8+16);
                    cp16(d8+32, s8+32); cp16(d8+48, s8+48);
                }
                CP_COMMIT();
            }
            // g2 -> Y rows 64-95
            CP_WAIT(1);
            {
                float4 v0 = *(const float4*)(sp0);
                float4 v1 = *(const float4*)(sp0 + 16);
                float4 v2 = *(const float4*)(sp0 + 32);
                float4 v3 = *(const float4*)(sp0 + 48);
                char* yd = ydst + (size_t)64*YROWB;
                cvt_store16(yd,      v0, v1);
                cvt_store16(yd + 16, v2, v3);
            }
            // g3 -> Y rows 96-127 (+ row 128)
            CP_WAIT(0);
            {
                float4 v0 = *(const float4*)(sp1);
                float4 v1 = *(const float4*)(sp1 + 16);
                float4 v2 = *(const float4*)(sp1 + 32);
                float4 v3 = *(const float4*)(sp1 + 48);
                char* yd = ydst + (size_t)96*YROWB;
                cvt_store16(yd,      v0, v1);
                cvt_store16(yd + 16, v2, v3);
                if (tid < 8) {
                    const char* s8 = smem + SM_S1 + 32*SROWB + tid*64;
                    float4 w0 = *(const float4*)(s8);
                    float4 w1 = *(const float4*)(s8 + 16);
                    float4 w2 = *(const float4*)(s8 + 32);
                    float4 w3 = *(const float4*)(s8 + 48);
                    char* y8 = smem + SM_Y + (size_t)128*YROWB + tid*32;
                    cvt_store16(y8,      w0, w1);
                    cvt_store16(y8 + 16, w2, w3);
                }
            }
            __syncthreads();  // Y writes visible to all before next mma
        }
    }

    // ================= final reduction (fixed order -> deterministic)
    #pragma unroll
    for (int off = 16; off; off >>= 1)
        csum += __shfl_down_sync(0xffffffffu, csum, off);
    __shared__ double redd[8];
    if (lane == 0) redd[w] = csum;
    __syncthreads();

    __shared__ bool is_last;
    if (tid == 0) {
        double s = 0.0;
        #pragma unroll
        for (int q = 0; q < 8; q++) s += redd[q];
        g_partials[cta] = s;
        __threadfence();
        unsigned int old = atomicAdd(&g_done, 1u);
        is_last = (old == (unsigned int)(NCTA - 1));
    }
    __syncthreads();

    if (is_last) {
        double s = (tid < NCTA) ? g_partials[tid] : 0.0;
        if (tid + 256 < NCTA) s += g_partials[tid + 256];
        __shared__ double sd[256];
        sd[tid] = s; __syncthreads();
        for (int off = 128; off; off >>= 1) {
            if (tid < off) sd[tid] += sd[tid + off];
            __syncthreads();
        }
        if (tid == 0) {
            double step_loss = sd[0] / ((double)ROWS * (double)H);
            double l2_loss   = g_l2 / ((double)H * (double)H);
            out[0] = (float)(step_loss + 0.001 * l2_loss);
            g_done = 0u; g_barA = 0u; g_barB = 0u;   // reset for graph replay
        }
    }
}

// ---------------------------------------------------------------- launch
extern "C" void kernel_launch(void* const* d_in, const int* in_sizes, int n_in,
                              void* d_out, int out_size) {
    const float* x     = (const float*)d_in[0];
    const float* coeff = (const float*)d_in[1];
    if (n_in >= 2 && in_sizes[0] == H*H) {
        coeff = (const float*)d_in[0];
        x     = (const float*)d_in[1];
    }
    float* out = (float*)d_out;

    cudaFuncSetAttribute(fused_kernel,
                         cudaFuncAttributeMaxDynamicSharedMemorySize, SMEM_TOTAL);

    fused_kernel<<<NCTA, 256, SMEM_TOTAL>>>(x, coeff, out);
}